// round 15
// baseline (speedup 1.0000x reference)
#include <cuda_runtime.h>
#include <cstdint>

// PatchNeighborSearcher: B=8, H=W=16 (P=256), L=64, C=64.
// out[b, p, l*8+n, c] = in[b, neighbor_p(n), l, c] if in-bounds else 0.
//
// Champion design (R4/R14): one thread per (b,l,h,w,c4), 8 predicated
// LDG.128 at compile-time-constant offsets (MLP=8), 8 coalesced evict-first
// STG.128. Pure ~256MB streaming-write drain at the ~5.4 TB/s sm_103a store
// ceiling; input (32MB) is L2-resident.
//
// This round: identical code, block size 256 -> 128 (finer CTA granularity,
// smoother tail across 148 SMs). Last untested launch parameter.
//
// Input  float4 idx: (b<<18)|(h<<14)|(w<<10)|(l<<4)|c4
// Output float4 idx: (b<<21)|(h<<17)|(w<<13)|(l<<7)|(n<<4)|c4

__global__ void __launch_bounds__(128) patch_neighbor_kernel(
    const float4* __restrict__ in, float4* __restrict__ out)
{
    int tid = blockIdx.x * blockDim.x + threadIdx.x;   // 2,097,152 threads

    int c4 = tid & 15;
    int w  = (tid >> 4) & 15;
    int h  = (tid >> 8) & 15;
    int l  = (tid >> 12) & 63;
    int b  = tid >> 18;

    int hm = (h > 0);
    int hp = (h < 15);
    int wm = (w > 0);
    int wp = (w < 15);

    // neighbor order: (-1,-1)(-1,0)(-1,1)(0,-1)(0,1)(1,-1)(1,0)(1,1)
    int valid[8] = { hm & wm, hm, hm & wp,
                     wm,          wp,
                     hp & wm, hp, hp & wp };

    // neighbor offset in float4 units: (dy*16 + dx) << 10
    constexpr int OFF[8] = {
        (-17) << 10, (-16) << 10, (-15) << 10,
        ( -1) << 10,               (  1) << 10,
        ( 15) << 10, ( 16) << 10, ( 17) << 10
    };

    int ibase = (b << 18) | (h << 14) | (w << 10) | (l << 4) | c4;
    int obase = (b << 21) | (h << 17) | (w << 13) | (l << 7) | c4;

    const float4 zero = make_float4(0.f, 0.f, 0.f, 0.f);
    float4 v[8];

    #pragma unroll
    for (int n = 0; n < 8; n++) {
        v[n] = valid[n] ? __ldg(&in[ibase + OFF[n]]) : zero;
    }

    #pragma unroll
    for (int n = 0; n < 8; n++) {
        __stcs(&out[obase + (n << 4)], v[n]);
    }
}

extern "C" void kernel_launch(void* const* d_in, const int* in_sizes, int n_in,
                              void* d_out, int out_size)
{
    const float4* in = (const float4*)d_in[0];
    float4* out = (float4*)d_out;

    int threads_total = (out_size / 4) / 8;   // 2,097,152
    int block = 128;
    int grid = (threads_total + block - 1) / block;
    patch_neighbor_kernel<<<grid, block>>>(in, out);
}

// round 16
// speedup vs baseline: 1.0222x; 1.0222x over previous
#include <cuda_runtime.h>
#include <cstdint>

// PatchNeighborSearcher: B=8, H=W=16 (P=256), L=64, C=64.
// out[b, p, l*8+n, c] = in[b, neighbor_p(n), l, c] if in-bounds else 0.
//
// FINAL kernel — champion across 15 measured variants (dur 47.58us best).
// The problem is a pure ~256MB streaming-write drain at the ~5.4 TB/s
// sm_103a store ceiling: input (32MB) is L2-resident, all SM pipes <=10%.
// Tested and rejected: v8.f32 accesses, L1 reuse tiling, SMEM staging,
// TMA bulk stores, persistent grid, L2 evict_last persistence (3 schemes),
// input prefetch pinning, write-contiguity remap, block sizes 128/persistent.
//
// One thread per (b,l,h,w,c4): 8 predicated LDG.128 at compile-time
// constant offsets (MLP=8), 8 coalesced evict-first STG.128. 28 regs,
// occ 84%, block=256 (measured optimum).
//
// Input  float4 idx: (b<<18)|(h<<14)|(w<<10)|(l<<4)|c4
// Output float4 idx: (b<<21)|(h<<17)|(w<<13)|(l<<7)|(n<<4)|c4

__global__ void __launch_bounds__(256) patch_neighbor_kernel(
    const float4* __restrict__ in, float4* __restrict__ out)
{
    int tid = blockIdx.x * blockDim.x + threadIdx.x;   // 2,097,152 threads

    int c4 = tid & 15;
    int w  = (tid >> 4) & 15;
    int h  = (tid >> 8) & 15;
    int l  = (tid >> 12) & 63;
    int b  = tid >> 18;

    int hm = (h > 0);
    int hp = (h < 15);
    int wm = (w > 0);
    int wp = (w < 15);

    // neighbor order: (-1,-1)(-1,0)(-1,1)(0,-1)(0,1)(1,-1)(1,0)(1,1)
    int valid[8] = { hm & wm, hm, hm & wp,
                     wm,          wp,
                     hp & wm, hp, hp & wp };

    // neighbor offset in float4 units: (dy*16 + dx) << 10
    constexpr int OFF[8] = {
        (-17) << 10, (-16) << 10, (-15) << 10,
        ( -1) << 10,               (  1) << 10,
        ( 15) << 10, ( 16) << 10, ( 17) << 10
    };

    int ibase = (b << 18) | (h << 14) | (w << 10) | (l << 4) | c4;
    int obase = (b << 21) | (h << 17) | (w << 13) | (l << 7) | c4;

    const float4 zero = make_float4(0.f, 0.f, 0.f, 0.f);
    float4 v[8];

    #pragma unroll
    for (int n = 0; n < 8; n++) {
        v[n] = valid[n] ? __ldg(&in[ibase + OFF[n]]) : zero;
    }

    #pragma unroll
    for (int n = 0; n < 8; n++) {
        __stcs(&out[obase + (n << 4)], v[n]);
    }
}

extern "C" void kernel_launch(void* const* d_in, const int* in_sizes, int n_in,
                              void* d_out, int out_size)
{
    const float4* in = (const float4*)d_in[0];
    float4* out = (float4*)d_out;

    int threads_total = (out_size / 4) / 8;   // 2,097,152
    int block = 256;
    int grid = (threads_total + block - 1) / block;
    patch_neighbor_kernel<<<grid, block>>>(in, out);
}